// round 5
// baseline (speedup 1.0000x reference)
#include <cuda_runtime.h>
#include <cuda_bf16.h>
#include <cstdint>
#include <math.h>

#define NB 16
#define CC 128
#define HW 64
#define EN 4
#define NPX 4096           // 64*64 pixels per image
#define NITER 72           // 8 ci-chunks * 9 taps

// SMEM map (dynamic): B halo [8 ck][264 px][80B] = 168960; W ring 6 x 8192 = 49152
#define B_STRIDE 80
#define B_CHUNK  21120     // 264 * 80
#define W_OFF    168960
#define SMEM_BYTES (168960 + 49152)

// ---------------- device scratch ----------------
__device__ int      g_sel[NB];
__device__ float    g_val[NB];
__device__ uint16_t g_xh[(size_t)NB*NPX*CC];   // x  hi bf16, [b][px][ci]
__device__ uint16_t g_xl[(size_t)NB*NPX*CC];   // x  lo bf16
__device__ uint16_t g_hh[(size_t)NB*NPX*CC];   // gelu(h) hi
__device__ uint16_t g_hl[(size_t)NB*NPX*CC];   // gelu(h) lo
__device__ uint16_t g_w1h[(size_t)EN*9*CC*CC]; // [e][tap][co][ci]
__device__ uint16_t g_w1l[(size_t)EN*9*CC*CC];
__device__ uint16_t g_w2h[(size_t)EN*9*CC*CC];
__device__ uint16_t g_w2l[(size_t)EN*9*CC*CC];

// ---------------- helpers ----------------
__device__ __forceinline__ uint32_t smem_u32(const void* p) {
    uint32_t a;
    asm("{ .reg .u64 t; cvta.to.shared.u64 t, %1; cvt.u32.u64 %0, t; }"
        : "=r"(a) : "l"(p));
    return a;
}
__device__ __forceinline__ void cp16(uint32_t d, const void* s, bool ok) {
    asm volatile("cp.async.cg.shared.global [%0], [%1], 16, %2;"
        :: "r"(d), "l"(s), "r"(ok ? 16u : 0u) : "memory");
}
#define CP_COMMIT() asm volatile("cp.async.commit_group;" ::: "memory")
#define CP_WAIT4()  asm volatile("cp.async.wait_group 4;" ::: "memory")
#define CP_WAIT0()  asm volatile("cp.async.wait_group 0;" ::: "memory")

#define LDM(r, a) \
    asm volatile("ldmatrix.sync.aligned.m8n8.x4.shared.b16 {%0,%1,%2,%3}, [%4];" \
        : "=r"((r)[0]), "=r"((r)[1]), "=r"((r)[2]), "=r"((r)[3]) : "r"(a))

#define MMA(c, a, b) \
    asm volatile("mma.sync.aligned.m16n8k16.row.col.f32.bf16.bf16.f32 " \
        "{%0,%1,%2,%3},{%4,%5,%6,%7},{%8,%9},{%0,%1,%2,%3};" \
        : "+f"((c)[0]), "+f"((c)[1]), "+f"((c)[2]), "+f"((c)[3]) \
        : "r"((a)[0]), "r"((a)[1]), "r"((a)[2]), "r"((a)[3]), \
          "r"((b)[0]), "r"((b)[1]))

__device__ __forceinline__ void split2(float v, uint16_t& h, uint16_t& l) {
    __nv_bfloat16 hb = __float2bfloat16(v);
    float r = v - __bfloat162float(hb);
    __nv_bfloat16 lb = __float2bfloat16(r);
    h = __bfloat16_as_ushort(hb);
    l = __bfloat16_as_ushort(lb);
}
__device__ __forceinline__ uint32_t pack_hl(float v) {
    uint16_t h, l; split2(v, h, l);
    return ((uint32_t)l << 16) | (uint32_t)h;
}
__device__ __forceinline__ float gelu_f(float v) {
    return 0.5f * v * (1.f + erff(v * 0.70710678118654752f));
}

// ---------------------------------------------------------------------------
__global__ void gate_kernel(const float* __restrict__ text, const float* __restrict__ gw)
{
    __shared__ float lg[EN];
    int b = blockIdx.x, wid = threadIdx.x >> 5, lid = threadIdx.x & 31;
    const float* tp = text + b * 512;
    const float* wp = gw + wid * 512;
    float s = 0.f;
    #pragma unroll 4
    for (int k = lid; k < 512; k += 32) s += tp[k] * wp[k];
    #pragma unroll
    for (int o = 16; o; o >>= 1) s += __shfl_xor_sync(~0u, s, o);
    if (lid == 0) lg[wid] = s;
    __syncthreads();
    if (threadIdx.x == 0) {
        float m = lg[0]; int am = 0;
        #pragma unroll
        for (int e = 1; e < EN; e++) if (lg[e] > m) { m = lg[e]; am = e; }
        float sum = 0.f;
        #pragma unroll
        for (int e = 0; e < EN; e++) sum += expf(lg[e] - m);
        g_sel[b] = am;
        g_val[b] = 1.f / sum;
    }
}

// w[e][co][ci][3][3] fp32 -> hi/lo bf16 at [e][tap][co][ci]
__global__ void prep_w_kernel(const float* __restrict__ w,
                              uint16_t* __restrict__ oh, uint16_t* __restrict__ ol)
{
    int g = blockIdx.x * blockDim.x + threadIdx.x;
    if (g >= EN * 9 * CC * CC) return;
    int ci = g & 127, co = (g >> 7) & 127, tap = (g >> 14) % 9, e = g / (9 * CC * CC);
    float v = w[((size_t)(e * CC + co) * CC + ci) * 9 + tap];
    uint16_t h, l; split2(v, h, l);
    oh[g] = h; ol[g] = l;
}

// x[b][ci][px] fp32 -> xT hi/lo [b][px][ci] (32x32 SMEM tile transpose)
__global__ void prep_x_kernel(const float* __restrict__ x)
{
    __shared__ float s[32][33];
    int b = blockIdx.z, ci0 = blockIdx.y * 32, px0 = blockIdx.x * 32;
    int pl = threadIdx.x & 31, cl = threadIdx.x >> 5;
    #pragma unroll
    for (int i = 0; i < 4; i++) {
        int ci = cl + i * 8;
        s[ci][pl] = x[((size_t)(b * CC + ci0 + ci)) * NPX + px0 + pl];
    }
    __syncthreads();
    #pragma unroll
    for (int i = 0; i < 4; i++) {
        int px = cl + i * 8;
        uint16_t h, l; split2(s[pl][px], h, l);
        size_t o = ((size_t)b * NPX + px0 + px) * CC + ci0 + pl;
        g_xh[o] = h; g_xl[o] = l;
    }
}

// ---------------------------------------------------------------------------
// Per CTA: image b, 128 px (2 output rows), 128 co. Persistent halo B in SMEM
// (4 rows x 66 cols x 8 ci-chunks); mainloop stages only 8KB weights/iter
// through a 6-deep cp.async ring. Split-bf16 3-product mma.sync.
template<bool L1>
__global__ void __launch_bounds__(256) conv_mma(const float* __restrict__ bias,
                                                float* __restrict__ out)
{
    extern __shared__ __align__(128) uint8_t dsm[];
    const int t = threadIdx.x, wid = t >> 5, lid = t & 31;
    const int b = blockIdx.y, y0 = blockIdx.x * 2;
    const int e = g_sel[b];
    const uint32_t sB = smem_u32(dsm);
    const uint32_t sW = sB + W_OFF;

    const uint16_t* __restrict__ wh = (L1 ? g_w1h : g_w2h) + (size_t)e * 9 * CC * CC;
    const uint16_t* __restrict__ wl = (L1 ? g_w1l : g_w2l) + (size_t)e * 9 * CC * CC;
    const uint16_t* __restrict__ xh = (L1 ? g_xh : g_hh) + (size_t)b * NPX * CC;
    const uint16_t* __restrict__ xl = (L1 ? g_xl : g_hl) + (size_t)b * NPX * CC;

    // ---- weight stage: thread -> (co row, k-half); one 16B granule hi + lo
    const int srow = t >> 1, skh = t & 1;
    const uint32_t wdo = srow * 32 + (((skh + (srow >> 2)) & 1) << 4);
    auto stageW = [&](int j) {           // j = iteration index = ck*9 + tap
        const int ck = j / 9, tap = j - ck * 9;
        const uint32_t d = sW + (j % 6) * 8192 + wdo;
        const size_t wo = ((size_t)tap * CC + srow) * CC + ck * 16 + skh * 8;
        cp16(d,        wh + wo, true);
        cp16(d + 4096, wl + wo, true);
    };

    // ---- prologue: stage full B halo (8448 granules) + first 5 weight stages
    for (int idx = t; idx < 8 * 264 * 4; idx += 256) {
        int g = idx & 3;                       // 0:hi kh0 1:hi kh1 2:lo kh0 3:lo kh1
        int rest = idx >> 2;
        int hp = rest % 264, ck = rest / 264;
        int hy = hp / 66, hx = hp - hy * 66;
        int gy = y0 - 1 + hy, gx = hx - 1;
        bool ok = ((unsigned)gy < HW) && ((unsigned)gx < HW);
        const uint16_t* base = (g & 2) ? xl : xh;
        size_t so = ok ? ((size_t)(gy * HW + gx) * CC + ck * 16 + (g & 1) * 8) : 0;
        cp16(sB + ck * B_CHUNK + hp * B_STRIDE + g * 16, base + so, ok);
    }
    stageW(0); CP_COMMIT();
    stageW(1); CP_COMMIT();
    stageW(2); CP_COMMIT();
    stageW(3); CP_COMMIT();
    stageW(4); CP_COMMIT();

    // ---- compute geometry
    const int Mw = (wid >> 2) * 64, Nw = (wid & 3) * 32;
    const int arow0 = (lid & 7) + (((lid >> 3) & 1) << 3);
    const int akh   = lid >> 4;
    const int brow0 = (lid & 7) + (((lid >> 4) & 1) << 3);
    const int bkh   = (lid >> 3) & 1;
    int hpb[2];
    #pragma unroll
    for (int np = 0; np < 2; np++) {
        int r = Nw + np * 16 + brow0;
        hpb[np] = ((r >> 6) + 1) * 66 + (r & 63) + 1;
    }
    const int TOFF[9] = {-67, -66, -65, -1, 0, 1, 65, 66, 67};

    float acc[4][4][4];
    #pragma unroll
    for (int mi = 0; mi < 4; mi++)
        #pragma unroll
        for (int nj = 0; nj < 4; nj++)
            #pragma unroll
            for (int k = 0; k < 4; k++) acc[mi][nj][k] = 0.f;

    // ---- mainloop: 8 ci-chunks x 9 taps
    int it = 0;
    #pragma unroll 1
    for (int ck = 0; ck < 8; ck++) {
        const uint32_t bB = sB + ck * B_CHUNK;
        #pragma unroll 1
        for (int tap = 0; tap < 9; tap++, it++) {
            CP_WAIT4();
            __syncthreads();
            if (it + 5 < NITER) stageW(it + 5);
            CP_COMMIT();                                  // empty groups keep counts uniform

            const uint32_t wbase = sW + (it % 6) * 8192;
            uint32_t aH[4][4], aL[4][4], bH[2][4], bL[2][4];
            #pragma unroll
            for (int mi = 0; mi < 4; mi++) {
                int r = Mw + mi * 16 + arow0;
                uint32_t ad = wbase + r * 32 + (((akh + (r >> 2)) & 1) << 4);
                LDM(aH[mi], ad);
                LDM(aL[mi], ad + 4096);
            }
            const int toff = TOFF[tap];
            #pragma unroll
            for (int np = 0; np < 2; np++) {
                uint32_t bd = bB + (uint32_t)(hpb[np] + toff) * B_STRIDE + bkh * 16;
                LDM(bH[np], bd);
                LDM(bL[np], bd + 32);
            }
            #pragma unroll
            for (int mi = 0; mi < 4; mi++)
                #pragma unroll
                for (int nj = 0; nj < 4; nj++) {
                    uint32_t* bh = &bH[nj >> 1][(nj & 1) * 2];
                    uint32_t* bl = &bL[nj >> 1][(nj & 1) * 2];
                    MMA(acc[mi][nj], aH[mi], bh);
                    MMA(acc[mi][nj], aH[mi], bl);
                    MMA(acc[mi][nj], aL[mi], bh);
                }
        }
    }
    CP_WAIT0();
    __syncthreads();

    // ---------------- epilogue (sT overlays the weight ring region) ----------------
    const float scale = g_val[b];
    uint8_t* epool = dsm + W_OFF;
    if (L1) {
        uint32_t* sT = (uint32_t*)epool;            // [32 px][132] packed hi|lo
        for (int r = 0; r < 4; r++) {
            if ((wid & 3) == r) {
                #pragma unroll
                for (int mi = 0; mi < 4; mi++) {
                    int co = Mw + mi * 16 + (lid >> 2);
                    float b0 = bias[e * CC + co], b1 = bias[e * CC + co + 8];
                    #pragma unroll
                    for (int nj = 0; nj < 4; nj++) {
                        int n = nj * 8 + (lid & 3) * 2;
                        float* c = acc[mi][nj];
                        sT[n * 132 + co]           = pack_hl(gelu_f(c[0] + b0));
                        sT[(n + 1) * 132 + co]     = pack_hl(gelu_f(c[1] + b0));
                        sT[n * 132 + co + 8]       = pack_hl(gelu_f(c[2] + b1));
                        sT[(n + 1) * 132 + co + 8] = pack_hl(gelu_f(c[3] + b1));
                    }
                }
            }
            __syncthreads();
            {
                int pl = t >> 3, cil = (t & 7) * 16;
                int n = r * 32 + pl;
                int gy = y0 + (n >> 6), gx = n & 63;
                size_t o = (size_t)b * NPX * CC + (size_t)(gy * HW + gx) * CC + cil;
                #pragma unroll
                for (int k = 0; k < 16; k++) {
                    uint32_t v = sT[pl * 132 + cil + k];
                    g_hh[o + k] = (uint16_t)v;
                    g_hl[o + k] = (uint16_t)(v >> 16);
                }
            }
            __syncthreads();
        }
    } else {
        float* sT = (float*)epool;                  // [128 co][36] fp32
        for (int r = 0; r < 4; r++) {
            if ((wid & 3) == r) {
                #pragma unroll
                for (int mi = 0; mi < 4; mi++) {
                    int co = Mw + mi * 16 + (lid >> 2);
                    float b0 = bias[e * CC + co], b1 = bias[e * CC + co + 8];
                    #pragma unroll
                    for (int nj = 0; nj < 4; nj++) {
                        int n = nj * 8 + (lid & 3) * 2;
                        float* c = acc[mi][nj];
                        sT[co * 36 + n]           = (c[0] + b0) * scale;
                        sT[co * 36 + n + 1]       = (c[1] + b0) * scale;
                        sT[(co + 8) * 36 + n]     = (c[2] + b1) * scale;
                        sT[(co + 8) * 36 + n + 1] = (c[3] + b1) * scale;
                    }
                }
            }
            __syncthreads();
            #pragma unroll
            for (int j = 0; j < 4; j++) {
                int co = j * 32 + (t >> 3);
                int f4 = t & 7;
                int n = r * 32 + f4 * 4;
                int gy = y0 + (n >> 6), gx = n & 63;
                float4 v = *(const float4*)&sT[co * 36 + f4 * 4];
                *(float4*)&out[((size_t)(b * CC + co)) * NPX + gy * HW + gx] = v;
            }
            __syncthreads();
        }
    }
}

// ---------------------------------------------------------------------------
extern "C" void kernel_launch(void* const* d_in, const int* in_sizes, int n_in,
                              void* d_out, int out_size)
{
    const float* x    = (const float*)d_in[0];
    const float* text = (const float*)d_in[1];
    const float* gw   = (const float*)d_in[2];
    const float* w1   = (const float*)d_in[3];
    const float* b1   = (const float*)d_in[4];
    const float* w2   = (const float*)d_in[5];
    const float* b2   = (const float*)d_in[6];
    float* out = (float*)d_out;

    static int smem_set = 0;
    if (!smem_set) {
        cudaFuncSetAttribute(conv_mma<true >,
            cudaFuncAttributeMaxDynamicSharedMemorySize, SMEM_BYTES);
        cudaFuncSetAttribute(conv_mma<false>,
            cudaFuncAttributeMaxDynamicSharedMemorySize, SMEM_BYTES);
        smem_set = 1;
    }

    gate_kernel<<<NB, 128>>>(text, gw);

    uint16_t *w1h, *w1l, *w2h, *w2l;
    cudaGetSymbolAddress((void**)&w1h, g_w1h);
    cudaGetSymbolAddress((void**)&w1l, g_w1l);
    cudaGetSymbolAddress((void**)&w2h, g_w2h);
    cudaGetSymbolAddress((void**)&w2l, g_w2l);
    const int wn = EN * 9 * CC * CC;
    prep_w_kernel<<<(wn + 255) / 256, 256>>>(w1, w1h, w1l);
    prep_w_kernel<<<(wn + 255) / 256, 256>>>(w2, w2h, w2l);

    dim3 pg(NPX / 32, CC / 32, NB);
    prep_x_kernel<<<pg, 256>>>(x);

    dim3 grid(HW / 2, NB);   // 32 x 16
    conv_mma<true ><<<grid, 256, SMEM_BYTES>>>(b1, nullptr);
    conv_mma<false><<<grid, 256, SMEM_BYTES>>>(b2, out);
}

// round 7
// speedup vs baseline: 1.6081x; 1.6081x over previous
#include <cuda_runtime.h>
#include <cuda_fp16.h>
#include <cstdint>
#include <math.h>

#define NB 16
#define CC 128
#define HW 64
#define EN 4
#define NPX 4096           // 64*64 pixels per image
#define NCHUNKS 72         // 9 taps * 8 ci-chunks of 16

// ---------------- device scratch ----------------
__device__ int      g_sel[NB];
__device__ float    g_val[NB];
__device__ uint16_t g_xh[(size_t)NB*NPX*CC];   // x  hi fp16, [b][px][ci]
__device__ uint16_t g_xl[(size_t)NB*NPX*CC];   // x  lo fp16
__device__ uint16_t g_hh[(size_t)NB*NPX*CC];   // gelu(h) hi
__device__ uint16_t g_hl[(size_t)NB*NPX*CC];   // gelu(h) lo
__device__ uint16_t g_w1[(size_t)EN*9*CC*CC];  // fp16 [e][tap][co][ci]
__device__ uint16_t g_w2[(size_t)EN*9*CC*CC];

// ---------------- helpers ----------------
__device__ __forceinline__ uint32_t smem_u32(const void* p) {
    uint32_t a;
    asm("{ .reg .u64 t; cvta.to.shared.u64 t, %1; cvt.u32.u64 %0, t; }"
        : "=r"(a) : "l"(p));
    return a;
}
__device__ __forceinline__ void cp16(uint32_t d, const void* s, bool ok) {
    asm volatile("cp.async.cg.shared.global [%0], [%1], 16, %2;"
        :: "r"(d), "l"(s), "r"(ok ? 16u : 0u) : "memory");
}
#define CP_COMMIT() asm volatile("cp.async.commit_group;" ::: "memory")
#define CP_WAIT1()  asm volatile("cp.async.wait_group 1;" ::: "memory")
#define CP_WAIT0()  asm volatile("cp.async.wait_group 0;" ::: "memory")

#define LDM(r, a) \
    asm volatile("ldmatrix.sync.aligned.m8n8.x4.shared.b16 {%0,%1,%2,%3}, [%4];" \
        : "=r"((r)[0]), "=r"((r)[1]), "=r"((r)[2]), "=r"((r)[3]) : "r"(a))

#define MMAH(c, a, b) \
    asm volatile("mma.sync.aligned.m16n8k16.row.col.f32.f16.f16.f32 " \
        "{%0,%1,%2,%3},{%4,%5,%6,%7},{%8,%9},{%0,%1,%2,%3};" \
        : "+f"((c)[0]), "+f"((c)[1]), "+f"((c)[2]), "+f"((c)[3]) \
        : "r"((a)[0]), "r"((a)[1]), "r"((a)[2]), "r"((a)[3]), \
          "r"((b)[0]), "r"((b)[1]))

__device__ __forceinline__ void split2h(float v, uint16_t& h, uint16_t& l) {
    __half hb = __float2half_rn(v);
    float r = v - __half2float(hb);
    __half lb = __float2half_rn(r);
    h = __half_as_ushort(hb);
    l = __half_as_ushort(lb);
}
__device__ __forceinline__ uint32_t pack_hl16(float v) {
    uint16_t h, l; split2h(v, h, l);
    return ((uint32_t)l << 16) | (uint32_t)h;
}
__device__ __forceinline__ float gelu_f(float v) {
    return 0.5f * v * (1.f + erff(v * 0.70710678118654752f));
}

// ---------------------------------------------------------------------------
__global__ void gate_kernel(const float* __restrict__ text, const float* __restrict__ gw)
{
    __shared__ float lg[EN];
    int b = blockIdx.x, wid = threadIdx.x >> 5, lid = threadIdx.x & 31;
    const float* tp = text + b * 512;
    const float* wp = gw + wid * 512;
    float s = 0.f;
    #pragma unroll 4
    for (int k = lid; k < 512; k += 32) s += tp[k] * wp[k];
    #pragma unroll
    for (int o = 16; o; o >>= 1) s += __shfl_xor_sync(~0u, s, o);
    if (lid == 0) lg[wid] = s;
    __syncthreads();
    if (threadIdx.x == 0) {
        float m = lg[0]; int am = 0;
        #pragma unroll
        for (int e = 1; e < EN; e++) if (lg[e] > m) { m = lg[e]; am = e; }
        float sum = 0.f;
        #pragma unroll
        for (int e = 0; e < EN; e++) sum += expf(lg[e] - m);
        g_sel[b] = am;
        g_val[b] = 1.f / sum;
    }
}

// w[e][co][ci][3][3] fp32 -> fp16 at [e][tap][co][ci]
__global__ void prep_w_kernel(const float* __restrict__ w, uint16_t* __restrict__ oh)
{
    int g = blockIdx.x * blockDim.x + threadIdx.x;
    if (g >= EN * 9 * CC * CC) return;
    int ci = g & 127, co = (g >> 7) & 127, tap = (g >> 14) % 9, e = g / (9 * CC * CC);
    float v = w[((size_t)(e * CC + co) * CC + ci) * 9 + tap];
    oh[g] = __half_as_ushort(__float2half_rn(v));
}

// x[b][ci][px] fp32 -> xT hi/lo fp16 [b][px][ci] (32x32 SMEM tile transpose)
__global__ void prep_x_kernel(const float* __restrict__ x)
{
    __shared__ float s[32][33];
    int b = blockIdx.z, ci0 = blockIdx.y * 32, px0 = blockIdx.x * 32;
    int pl = threadIdx.x & 31, cl = threadIdx.x >> 5;
    #pragma unroll
    for (int i = 0; i < 4; i++) {
        int ci = cl + i * 8;
        s[ci][pl] = x[((size_t)(b * CC + ci0 + ci)) * NPX + px0 + pl];
    }
    __syncthreads();
    #pragma unroll
    for (int i = 0; i < 4; i++) {
        int px = cl + i * 8;
        uint16_t h, l; split2h(s[pl][px], h, l);
        size_t o = ((size_t)b * NPX + px0 + px) * CC + ci0 + pl;
        g_xh[o] = h; g_xl[o] = l;
    }
}

// ---------------------------------------------------------------------------
// Per CTA: image b, 128 pixels (2 rows), 128 co. mma.sync m16n8k16 fp16.
// Weights single fp16; activations split hi/lo (2 MMAs per tile).
// Double-buffered cp.async staging, 12KB/stage: W@0, Bhi@4096, Blo@8192;
// each matrix 128 rows x 32B, 16B halves swizzled by ((kh + (row>>2)) & 1).
template<bool L1>
__global__ void __launch_bounds__(256) conv_mma(const float* __restrict__ bias,
                                                float* __restrict__ out)
{
    __shared__ __align__(16) uint8_t pool[24576];
    const int t = threadIdx.x, wid = t >> 5, lid = t & 31;
    const int b = blockIdx.y, y0 = blockIdx.x * 2;
    const int e = g_sel[b];
    const uint32_t sb = smem_u32(pool);

    const uint16_t* __restrict__ wp = (L1 ? g_w1 : g_w2) + (size_t)e * 9 * CC * CC;
    const uint16_t* __restrict__ xh = (L1 ? g_xh : g_hh) + (size_t)b * NPX * CC;
    const uint16_t* __restrict__ xl = (L1 ? g_xl : g_hl) + (size_t)b * NPX * CC;

    // staging: thread -> (row 0..127, k-half 0..1), one 16B granule per matrix
    const int srow = t >> 1, skh = t & 1;
    const uint32_t sdo = srow * 32 + (((skh + (srow >> 2)) & 1) << 4);

    auto stage = [&](int it, int buf) {
        const int tap = it >> 3, ci0 = (it & 7) << 4;
        const int ty = tap / 3;
        const int dy = ty - 1, dx = tap - ty * 3 - 1;
        const uint32_t d = sb + buf * 12288 + sdo;
        cp16(d, wp + ((size_t)tap * CC + srow) * CC + ci0 + skh * 8, true);
        const int gy = y0 + (srow >> 6) + dy, gx = (srow & 63) + dx;
        const bool ok = ((unsigned)gy < HW) && ((unsigned)gx < HW);
        const size_t po = ok ? ((size_t)(gy * HW + gx) * CC + ci0 + skh * 8) : 0;
        cp16(d + 4096, xh + po, ok);
        cp16(d + 8192, xl + po, ok);
        CP_COMMIT();
    };

    // compute geometry
    const int Mw = (wid >> 2) * 64, Nw = (wid & 3) * 32;
    const int arow0 = (lid & 7) + (((lid >> 3) & 1) << 3);
    const int akh   = lid >> 4;
    const int brow0 = (lid & 7) + (((lid >> 4) & 1) << 3);
    const int bkh   = (lid >> 3) & 1;

    float acc[4][4][4];
    #pragma unroll
    for (int mi = 0; mi < 4; mi++)
        #pragma unroll
        for (int nj = 0; nj < 4; nj++)
            #pragma unroll
            for (int k = 0; k < 4; k++) acc[mi][nj][k] = 0.f;

    stage(0, 0);
    for (int it = 0; it < NCHUNKS; it++) {
        if (it + 1 < NCHUNKS) { stage(it + 1, (it + 1) & 1); CP_WAIT1(); }
        else                  { CP_WAIT0(); }
        __syncthreads();
        const uint32_t base = sb + (it & 1) * 12288;

        uint32_t aF[4][4], bH[2][4], bL[2][4];
        #pragma unroll
        for (int mi = 0; mi < 4; mi++) {
            int r = Mw + mi * 16 + arow0;
            LDM(aF[mi], base + r * 32 + (((akh + (r >> 2)) & 1) << 4));
        }
        #pragma unroll
        for (int np = 0; np < 2; np++) {
            int r = Nw + np * 16 + brow0;
            uint32_t bd = base + 4096 + r * 32 + (((bkh + (r >> 2)) & 1) << 4);
            LDM(bH[np], bd);
            LDM(bL[np], bd + 4096);
        }
        #pragma unroll
        for (int mi = 0; mi < 4; mi++)
            #pragma unroll
            for (int nj = 0; nj < 4; nj++) {
                uint32_t* bh = &bH[nj >> 1][(nj & 1) * 2];
                uint32_t* bl = &bL[nj >> 1][(nj & 1) * 2];
                MMAH(acc[mi][nj], aF[mi], bh);
                MMAH(acc[mi][nj], aF[mi], bl);
            }
        __syncthreads();
    }

    // ---------------- epilogue ----------------
    const float scale = g_val[b];
    if (L1) {
        uint32_t* sT = (uint32_t*)pool;             // [32 px][132] packed hi|lo fp16
        for (int r = 0; r < 4; r++) {
            if ((wid & 3) == r) {
                #pragma unroll
                for (int mi = 0; mi < 4; mi++) {
                    int co = Mw + mi * 16 + (lid >> 2);
                    float b0 = bias[e * CC + co], b1 = bias[e * CC + co + 8];
                    #pragma unroll
                    for (int nj = 0; nj < 4; nj++) {
                        int n = nj * 8 + (lid & 3) * 2;
                        float* c = acc[mi][nj];
                        sT[n * 132 + co]           = pack_hl16(gelu_f(c[0] + b0));
                        sT[(n + 1) * 132 + co]     = pack_hl16(gelu_f(c[1] + b0));
                        sT[n * 132 + co + 8]       = pack_hl16(gelu_f(c[2] + b1));
                        sT[(n + 1) * 132 + co + 8] = pack_hl16(gelu_f(c[3] + b1));
                    }
                }
            }
            __syncthreads();
            {
                int pl = t >> 3, cil = (t & 7) * 16;
                int n = r * 32 + pl;
                int gy = y0 + (n >> 6), gx = n & 63;
                size_t o = (size_t)b * NPX * CC + (size_t)(gy * HW + gx) * CC + cil;
                #pragma unroll
                for (int k = 0; k < 16; k++) {
                    uint32_t v = sT[pl * 132 + cil + k];
                    g_hh[o + k] = (uint16_t)v;
                    g_hl[o + k] = (uint16_t)(v >> 16);
                }
            }
            __syncthreads();
        }
    } else {
        float* sT = (float*)pool;                   // [128 co][36] fp32
        for (int r = 0; r < 4; r++) {
            if ((wid & 3) == r) {
                #pragma unroll
                for (int mi = 0; mi < 4; mi++) {
                    int co = Mw + mi * 16 + (lid >> 2);
                    float b0 = bias[e * CC + co], b1 = bias[e * CC + co + 8];
                    #pragma unroll
                    for (int nj = 0; nj < 4; nj++) {
                        int n = nj * 8 + (lid & 3) * 2;
                        float* c = acc[mi][nj];
                        sT[co * 36 + n]           = (c[0] + b0) * scale;
                        sT[co * 36 + n + 1]       = (c[1] + b0) * scale;
                        sT[(co + 8) * 36 + n]     = (c[2] + b1) * scale;
                        sT[(co + 8) * 36 + n + 1] = (c[3] + b1) * scale;
                    }
                }
            }
            __syncthreads();
            #pragma unroll
            for (int j = 0; j < 4; j++) {
                int co = j * 32 + (t >> 3);
                int f4 = t & 7;
                int n = r * 32 + f4 * 4;
                int gy = y0 + (n >> 6), gx = n & 63;
                float4 v = *(const float4*)&sT[co * 36 + f4 * 4];
                *(float4*)&out[((size_t)(b * CC + co)) * NPX + gy * HW + gx] = v;
            }
            __syncthreads();
        }
    }
}

// ---------------------------------------------------------------------------
extern "C" void kernel_launch(void* const* d_in, const int* in_sizes, int n_in,
                              void* d_out, int out_size)
{
    const float* x    = (const float*)d_in[0];
    const float* text = (const float*)d_in[1];
    const float* gw   = (const float*)d_in[2];
    const float* w1   = (const float*)d_in[3];
    const float* b1   = (const float*)d_in[4];
    const float* w2   = (const float*)d_in[5];
    const float* b2   = (const float*)d_in[6];
    float* out = (float*)d_out;

    gate_kernel<<<NB, 128>>>(text, gw);

    uint16_t *w1p, *w2p;
    cudaGetSymbolAddress((void**)&w1p, g_w1);
    cudaGetSymbolAddress((void**)&w2p, g_w2);
    const int wn = EN * 9 * CC * CC;
    prep_w_kernel<<<(wn + 255) / 256, 256>>>(w1, w1p);
    prep_w_kernel<<<(wn + 255) / 256, 256>>>(w2, w2p);

    dim3 pg(NPX / 32, CC / 32, NB);
    prep_x_kernel<<<pg, 256>>>(x);

    dim3 grid(HW / 2, NB);   // 32 x 16
    conv_mma<true ><<<grid, 256>>>(b1, nullptr);
    conv_mma<false><<<grid, 256>>>(b2, out);
}